// round 4
// baseline (speedup 1.0000x reference)
#include <cuda_runtime.h>
#include <cstdint>
#include <float.h>

#define NB    4
#define NPTS  8192
#define NPQ   2048
#define NCH   128
#define CSZ   8            // cluster size (CTAs per batch)
#define PPC   (NPTS / CSZ) // points per CTA = 1024
#define FPT   256          // fps threads per CTA

// ---------------- device scratch (statically allocated; no cudaMalloc) ----------------
__device__ float4 g_p4[NB * NPTS];                    // (x,y,z,|p|^2)
__device__ float4 g_q4[NB * NPQ];                     // sampled points
__device__ int    g_fps[NB * NPQ];
__device__ float  g_feat_t[(size_t)NB * NPTS * NCH];  // features transposed [B,N,C]
__device__ float  g_coarse_t[(size_t)NB * NPQ * NCH]; // pooled features [B,q,C]
__device__ int    g_i3[NB * NPTS * 3];
__device__ float  g_w3[NB * NPTS * 3];

typedef unsigned long long u64;

// ---------------- packed f32x2 helpers ----------------
__device__ __forceinline__ u64 pk2(float a, float b) {
    u64 r; asm("mov.b64 %0, {%1,%2};" : "=l"(r) : "f"(a), "f"(b)); return r;
}
__device__ __forceinline__ void upk2(u64 v, float& a, float& b) {
    asm("mov.b64 {%0,%1}, %2;" : "=f"(a), "=f"(b) : "l"(v));
}
__device__ __forceinline__ u64 add2(u64 a, u64 b) {
    u64 r; asm("add.rn.f32x2 %0, %1, %2;" : "=l"(r) : "l"(a), "l"(b)); return r;
}
__device__ __forceinline__ u64 mul2(u64 a, u64 b) {
    u64 r; asm("mul.rn.f32x2 %0, %1, %2;" : "=l"(r) : "l"(a), "l"(b)); return r;
}
__device__ __forceinline__ u64 fma2(u64 a, u64 b, u64 c) {
    u64 r; asm("fma.rn.f32x2 %0, %1, %2, %3;" : "=l"(r) : "l"(a), "l"(b), "l"(c)); return r;
}

__device__ __forceinline__ uint32_t smem_u32(const void* p) {
    uint32_t a;
    asm("{ .reg .u64 t; cvta.to.shared.u64 t, %1; cvt.u32.u64 %0, t; }" : "=r"(a) : "l"(p));
    return a;
}
__device__ __forceinline__ uint32_t mapa_u32(uint32_t local, uint32_t rank) {
    uint32_t r; asm("mapa.shared::cluster.u32 %0, %1, %2;" : "=r"(r) : "r"(local), "r"(rank));
    return r;
}

// ---------------- prep: pack points + squared norm ----------------
__global__ void prep_kernel(const float* __restrict__ pts) {
    int i = blockIdx.x * 256 + threadIdx.x;          // over NB*NPTS
    float x = pts[3 * i], y = pts[3 * i + 1], z = pts[3 * i + 2];
    float nr = __fmaf_rn(z, z, __fmaf_rn(y, y, x * x));
    g_p4[i] = make_float4(x, y, z, nr);
}

// ---------------- transpose features [B,C,N] -> [B,N,C] ----------------
__global__ void transpose_kernel(const float* __restrict__ f) {
    __shared__ float tile[32][33];
    int b = blockIdx.z;
    int c0 = blockIdx.y * 32, n0 = blockIdx.x * 32;
    tile[threadIdx.y][threadIdx.x] =
        f[((size_t)b * NCH + c0 + threadIdx.y) * NPTS + n0 + threadIdx.x];
    __syncthreads();
    g_feat_t[((size_t)b * NPTS + n0 + threadIdx.y) * NCH + c0 + threadIdx.x] =
        tile[threadIdx.x][threadIdx.y];
}

// ---------------- FPS: 8-CTA cluster per batch, mbarrier DSMEM sync ----------------
// Each CTA owns 1024 points (4/thread, 2 packed pairs). Per iteration:
// local update + strict-> argmax tree + REDUX warp reduce -> per-warp keys in
// smem -> bar -> all warps redundantly reduce 8 warp keys -> CTA key -> tid0
// stores key into every cluster CTA's double-buffered slot (st.shared::cluster)
// and arrives (release.cluster) on every CTA's mbarrier (count=8). All threads
// try_wait (acquire.cluster), lanes 0-7 load the 8 slots, 2 REDUX -> identical
// nxt in every thread of the cluster. Tie rule everywhere = lowest global index
// (matches jnp.argmax first-occurrence). Arithmetic identical to reference.
__global__ void __launch_bounds__(FPT, 1) __cluster_dims__(CSZ, 1, 1) fps_kernel() {
    const int bid  = blockIdx.x;
    const int b    = bid >> 3;          // batch
    const int rank = bid & 7;           // cluster rank
    const int tid  = threadIdx.x;
    const int lane = tid & 31;
    const int wid  = tid >> 5;
    const float4* __restrict__ P = g_p4 + b * NPTS;

    __shared__ u64 swarp[FPT / 32];     // 8 per-warp keys
    __shared__ u64 cslot[2][CSZ];       // double-buffered per-CTA keys
    __shared__ u64 mbar;

    const uint32_t mb_a   = smem_u32(&mbar);
    const uint32_t slot_a = smem_u32(&cslot[0][rank]);

    if (tid == 0) {
        asm volatile("mbarrier.init.shared.b64 [%0], %1;" :: "r"(mb_a), "r"(CSZ) : "memory");
        if (rank == 0) g_fps[b * NPQ] = 0;
    }
    asm volatile("barrier.cluster.arrive.aligned;" ::: "memory");
    asm volatile("barrier.cluster.wait.aligned;"   ::: "memory");

    // local points: pair i at n = rank*1024 + i*512 + tid*2 + {0,1}
    u64 X[2], Y[2], Z[2];
    float dist[4];
#pragma unroll
    for (int i = 0; i < 2; i++) {
        int n0 = rank * PPC + i * 512 + tid * 2;
        float4 a = P[n0];
        float4 c = P[n0 + 1];
        X[i] = pk2(a.x, c.x); Y[i] = pk2(a.y, c.y); Z[i] = pk2(a.z, c.z);
    }
    const unsigned ibase = rank * PPC + tid * 2;

    // ---- iteration 0: d0 = ||x - x0||^2, post key into buffer 0 ----
    {
        float4 q0 = P[0];
        u64 ax = pk2(-q0.x, -q0.x), ay = pk2(-q0.y, -q0.y), az = pk2(-q0.z, -q0.z);
#pragma unroll
        for (int i = 0; i < 2; i++) {
            u64 dx = add2(X[i], ax), dy = add2(Y[i], ay), dz = add2(Z[i], az);
            u64 t = fma2(dz, dz, fma2(dy, dy, mul2(dx, dx)));
            upk2(t, dist[2 * i], dist[2 * i + 1]);
        }
    }

    int ph = 0;
    for (int j = 1; j < NPQ; j++) {
        // ---- local argmax tree over 4 dists (strict > keeps lowest index) ----
        float m0 = dist[0]; int k0 = 0;
        if (dist[1] > m0) { m0 = dist[1]; k0 = 1; }
        float m1 = dist[2]; int k1 = 2;
        if (dist[3] > m1) { m1 = dist[3]; k1 = 3; }
        if (m1 > m0) { m0 = m1; k0 = k1; }
        unsigned myidx = ibase + ((unsigned)(k0 >> 1) << 9) + (k0 & 1);
        unsigned db    = __float_as_uint(m0);     // dist >= 0 -> bits monotone
        unsigned wmax  = __reduce_max_sync(0xffffffffu, db);
        unsigned cand  = (db == wmax) ? myidx : 0xffffffffu;
        unsigned widx  = __reduce_min_sync(0xffffffffu, cand);
        if (lane == 0) swarp[wid] = ((u64)wmax << 32) | widx;
        __syncthreads();                           // swarp ready; slot reads done

        // ---- CTA-level reduce of 8 warp keys (redundant in every warp) ----
        u64 wk = swarp[lane & 7];
        unsigned whi = (unsigned)(wk >> 32), wlo = (unsigned)wk;
        unsigned cg  = __reduce_max_sync(0xffffffffu, whi);
        unsigned cc  = (whi == cg) ? wlo : 0xffffffffu;
        unsigned cidx = __reduce_min_sync(0xffffffffu, cc);
        u64 ckey = ((u64)cg << 32) | cidx;

        // ---- tid0 posts CTA key to all 8 CTAs + arrives on their mbarriers ----
        int wbuf = (j - 1) & 1;
        if (tid == 0) {
            uint32_t sl = slot_a + (uint32_t)(wbuf * CSZ * 8);
#pragma unroll
            for (int r = 0; r < CSZ; r++)
                asm volatile("st.shared::cluster.u64 [%0], %1;"
                             :: "r"(mapa_u32(sl, r)), "l"(ckey) : "memory");
#pragma unroll
            for (int r = 0; r < CSZ; r++)
                asm volatile("mbarrier.arrive.release.cluster.shared::cluster.b64 _, [%0];"
                             :: "r"(mapa_u32(mb_a, r)) : "memory");
        }

        // ---- wait for all 8 CTA keys ----
        {
            uint32_t done;
            do {
                asm volatile(
                    "{\n\t.reg .pred p;\n\t"
                    "mbarrier.try_wait.parity.acquire.cluster.shared::cta.b64 p, [%1], %2, 0x989680;\n\t"
                    "selp.b32 %0, 1, 0, p;\n\t}"
                    : "=r"(done) : "r"(mb_a), "r"((unsigned)ph) : "memory");
            } while (!done);
            ph ^= 1;
        }

        // ---- cluster reduce of 8 CTA keys (redundant in every warp) ----
        u64 kk = cslot[wbuf][lane & 7];
        unsigned hi = (unsigned)(kk >> 32), lo = (unsigned)kk;
        unsigned g2 = __reduce_max_sync(0xffffffffu, hi);
        unsigned c2 = (hi == g2) ? lo : 0xffffffffu;
        unsigned nxt = __reduce_min_sync(0xffffffffu, c2);
        if (rank == 0 && tid == 0) g_fps[b * NPQ + j] = (int)nxt;

        // ---- distance update vs new point (identical fma chain to reference) ----
        float4 qq = P[nxt];
        u64 ax = pk2(-qq.x, -qq.x), ay = pk2(-qq.y, -qq.y), az = pk2(-qq.z, -qq.z);
#pragma unroll
        for (int i = 0; i < 2; i++) {
            u64 dx = add2(X[i], ax), dy = add2(Y[i], ay), dz = add2(Z[i], az);
            u64 t = fma2(dz, dz, fma2(dy, dy, mul2(dx, dx)));
            float a, c; upk2(t, a, c);
            dist[2 * i]     = fminf(dist[2 * i], a);
            dist[2 * i + 1] = fminf(dist[2 * i + 1], c);
        }
    }
}

// ---------------- gather sampled coords ----------------
__global__ void gather_q4_kernel() {
    int i = blockIdx.x * 256 + threadIdx.x;          // over NB*NPQ
    int b = i >> 11;
    g_q4[i] = g_p4[b * NPTS + g_fps[i]];
}

// ---------------- kNN (top-17 smallest, drop nearest) + mean-pool features ----------------
__global__ void __launch_bounds__(256) knn_group_kernel() {
    int gw   = blockIdx.x * 8 + (threadIdx.x >> 5);  // global query id = b*NPQ + qi
    int lane = threadIdx.x & 31;
    int b    = gw >> 11;

    float4 q = g_q4[gw];
    const float4* __restrict__ P = g_p4 + b * NPTS;

    float d[17]; int id[17];
#pragma unroll
    for (int t = 0; t < 17; t++) { d[t] = FLT_MAX; id[t] = 0x7fffffff; }

    // lane-local sorted top-17 over 256 strided candidates
    for (int t = 0; t < NPTS / 32; t++) {
        int n = t * 32 + lane;
        float4 p = P[n];
        float dot = __fmaf_rn(q.z, p.z, __fmaf_rn(q.y, p.y, q.x * p.x));
        float sq  = fmaxf(__fmaf_rn(-2.f, dot, q.w + p.w), 0.f);
        if (sq < d[16]) {
            d[16] = sq; id[16] = n;
#pragma unroll
            for (int jj = 16; jj > 0; jj--) {
                if (d[jj] < d[jj - 1]) {
                    float td = d[jj]; d[jj] = d[jj - 1]; d[jj - 1] = td;
                    int   ti = id[jj]; id[jj] = id[jj - 1]; id[jj - 1] = ti;
                }
            }
        }
    }

    // 17-round k-way merge across lanes; skip round 0 (self/nearest), accumulate 16 nbrs
    float4 acc = make_float4(0.f, 0.f, 0.f, 0.f);
    const float* Fb = g_feat_t + (size_t)b * NPTS * NCH;
    u64 key = ((u64)__float_as_uint(d[0]) << 32) | (unsigned)id[0];
    for (int r = 0; r < 17; r++) {
        u64 m = key;
#pragma unroll
        for (int s = 16; s > 0; s >>= 1) {
            u64 o = __shfl_xor_sync(0xffffffffu, m, s);
            m = (o < m) ? o : m;
        }
        if (r > 0) {
            int nn = (int)(unsigned)m;
            const float4* row = (const float4*)(Fb + (size_t)nn * NCH);
            float4 f = row[lane];
            acc.x += f.x; acc.y += f.y; acc.z += f.z; acc.w += f.w;
        }
        if (key == m) {
#pragma unroll
            for (int jj = 0; jj < 16; jj++) { d[jj] = d[jj + 1]; id[jj] = id[jj + 1]; }
            d[16] = FLT_MAX; id[16] = 0x7fffffff;
        }
        key = ((u64)__float_as_uint(d[0]) << 32) | (unsigned)id[0];
    }

    float4 o = make_float4(acc.x * 0.0625f, acc.y * 0.0625f,
                           acc.z * 0.0625f, acc.w * 0.0625f);
    ((float4*)(g_coarse_t + (size_t)gw * NCH))[lane] = o;
}

// ---------------- three_nn: 3 nearest sampled points + inverse-distance weights ----------------
__global__ void __launch_bounds__(256) three_nn_kernel() {
    int b = blockIdx.y;
    int n = blockIdx.x * 256 + threadIdx.x;
    __shared__ float4 sq4[NPQ];
    for (int i = threadIdx.x; i < NPQ; i += 256) sq4[i] = g_q4[b * NPQ + i];
    __syncthreads();

    float4 p = g_p4[b * NPTS + n];
    float d0 = FLT_MAX, d1 = FLT_MAX, d2 = FLT_MAX;
    int   i0 = 0, i1 = 0, i2 = 0;
    for (int j = 0; j < NPQ; j++) {
        float4 q = sq4[j];
        float dot = __fmaf_rn(q.z, p.z, __fmaf_rn(q.y, p.y, q.x * p.x));
        float s   = fmaxf(__fmaf_rn(-2.f, dot, q.w + p.w), 0.f);
        bool c2 = s < d2, c1 = s < d1, c0 = s < d0;
        d2 = c1 ? d1 : (c2 ? s : d2);
        i2 = c1 ? i1 : (c2 ? j : i2);
        d1 = c0 ? d0 : (c1 ? s : d1);
        i1 = c0 ? i0 : (c1 ? j : i1);
        d0 = c0 ? s : d0;
        i0 = c0 ? j : i0;
    }
    d0 = fmaxf(d0, 1e-10f); d1 = fmaxf(d1, 1e-10f); d2 = fmaxf(d2, 1e-10f);
    float v0 = __fdiv_rn(1.f, d0 + 1e-8f);
    float v1 = __fdiv_rn(1.f, d1 + 1e-8f);
    float v2 = __fdiv_rn(1.f, d2 + 1e-8f);
    float ss = v0 + v1 + v2;
    int o = (b * NPTS + n) * 3;
    g_i3[o] = i0; g_i3[o + 1] = i1; g_i3[o + 2] = i2;
    g_w3[o]     = __fdiv_rn(v0, ss);
    g_w3[o + 1] = __fdiv_rn(v1, ss);
    g_w3[o + 2] = __fdiv_rn(v2, ss);
}

// ---------------- interpolate: out[b,c,n] = sum_k w_k * coarse[b, i3_k, c] ----------------
__global__ void __launch_bounds__(256) interp_kernel(float* __restrict__ out) {
    int b    = blockIdx.y;
    int n    = blockIdx.x * 8 + threadIdx.y;
    int lane = threadIdx.x;                           // float4-channel index
    int o = (b * NPTS + n) * 3;
    int a0 = g_i3[o], a1 = g_i3[o + 1], a2 = g_i3[o + 2];
    float w0 = g_w3[o], w1 = g_w3[o + 1], w2 = g_w3[o + 2];

    const float4* C = (const float4*)g_coarse_t + (size_t)b * NPQ * (NCH / 4);
    float4 f0 = C[a0 * (NCH / 4) + lane];
    float4 f1 = C[a1 * (NCH / 4) + lane];
    float4 f2 = C[a2 * (NCH / 4) + lane];

    float4 r;
    r.x = __fmaf_rn(f2.x, w2, __fmaf_rn(f1.x, w1, f0.x * w0));
    r.y = __fmaf_rn(f2.y, w2, __fmaf_rn(f1.y, w1, f0.y * w0));
    r.z = __fmaf_rn(f2.z, w2, __fmaf_rn(f1.z, w1, f0.z * w0));
    r.w = __fmaf_rn(f2.w, w2, __fmaf_rn(f1.w, w1, f0.w * w0));

    float* op = out + (size_t)b * NCH * NPTS + n;
    int c = lane * 4;
    op[(size_t)(c + 0) * NPTS] = r.x;
    op[(size_t)(c + 1) * NPTS] = r.y;
    op[(size_t)(c + 2) * NPTS] = r.z;
    op[(size_t)(c + 3) * NPTS] = r.w;
}

// ---------------- launch ----------------
extern "C" void kernel_launch(void* const* d_in, const int* in_sizes, int n_in,
                              void* d_out, int out_size) {
    const float* points   = (const float*)d_in[0];
    const float* features = (const float*)d_in[1];
    for (int i = 0; i < n_in; i++) {
        if (in_sizes[i] == NB * NPTS * 3)            points   = (const float*)d_in[i];
        else if (in_sizes[i] == NB * NCH * NPTS)     features = (const float*)d_in[i];
    }
    float* out = (float*)d_out;

    prep_kernel<<<(NB * NPTS) / 256, 256>>>(points);
    transpose_kernel<<<dim3(NPTS / 32, NCH / 32, NB), dim3(32, 32)>>>(features);
    fps_kernel<<<NB * CSZ, FPT>>>();
    gather_q4_kernel<<<(NB * NPQ) / 256, 256>>>();
    knn_group_kernel<<<(NB * NPQ) / 8, 256>>>();
    three_nn_kernel<<<dim3(NPTS / 256, NB), 256>>>();
    interp_kernel<<<dim3(NPTS / 8, NB), dim3(32, 8)>>>(out);
}

// round 5
// speedup vs baseline: 3.4223x; 3.4223x over previous
#include <cuda_runtime.h>
#include <cstdint>
#include <float.h>

#define NB    4
#define NPTS  8192
#define NPQ   2048
#define NCH   128

// ---------------- device scratch (statically allocated; no cudaMalloc) ----------------
__device__ float4 g_p4[NB * NPTS];                    // (x,y,z,|p|^2)
__device__ float4 g_q4[NB * NPQ];                     // sampled points
__device__ int    g_fps[NB * NPQ];
__device__ float  g_feat_t[(size_t)NB * NPTS * NCH];  // features transposed [B,N,C]
__device__ float  g_coarse_t[(size_t)NB * NPQ * NCH]; // pooled features [B,q,C]
__device__ int    g_i3[NB * NPTS * 3];
__device__ float  g_w3[NB * NPTS * 3];

typedef unsigned long long u64;

// ---------------- packed f32x2 helpers ----------------
__device__ __forceinline__ u64 pk2(float a, float b) {
    u64 r; asm("mov.b64 %0, {%1,%2};" : "=l"(r) : "f"(a), "f"(b)); return r;
}
__device__ __forceinline__ void upk2(u64 v, float& a, float& b) {
    asm("mov.b64 {%0,%1}, %2;" : "=f"(a), "=f"(b) : "l"(v));
}
__device__ __forceinline__ u64 add2(u64 a, u64 b) {
    u64 r; asm("add.rn.f32x2 %0, %1, %2;" : "=l"(r) : "l"(a), "l"(b)); return r;
}
__device__ __forceinline__ u64 mul2(u64 a, u64 b) {
    u64 r; asm("mul.rn.f32x2 %0, %1, %2;" : "=l"(r) : "l"(a), "l"(b)); return r;
}
__device__ __forceinline__ u64 fma2(u64 a, u64 b, u64 c) {
    u64 r; asm("fma.rn.f32x2 %0, %1, %2, %3;" : "=l"(r) : "l"(a), "l"(b), "l"(c)); return r;
}

// ---------------- prep: pack points + squared norm ----------------
__global__ void prep_kernel(const float* __restrict__ pts) {
    int i = blockIdx.x * 256 + threadIdx.x;          // over NB*NPTS
    float x = pts[3 * i], y = pts[3 * i + 1], z = pts[3 * i + 2];
    float nr = __fmaf_rn(z, z, __fmaf_rn(y, y, x * x));
    g_p4[i] = make_float4(x, y, z, nr);
}

// ---------------- transpose features [B,C,N] -> [B,N,C] ----------------
__global__ void transpose_kernel(const float* __restrict__ f) {
    __shared__ float tile[32][33];
    int b = blockIdx.z;
    int c0 = blockIdx.y * 32, n0 = blockIdx.x * 32;
    tile[threadIdx.y][threadIdx.x] =
        f[((size_t)b * NCH + c0 + threadIdx.y) * NPTS + n0 + threadIdx.x];
    __syncthreads();
    g_feat_t[((size_t)b * NPTS + n0 + threadIdx.y) * NCH + c0 + threadIdx.x] =
        tile[threadIdx.x][threadIdx.y];
}

// ---------------- FPS: one CTA per batch, 1024 threads, 8 pts/thread ----------------
// Two-phase, single-SM. Per iter: (A) all threads learn gmax via per-warp
// REDUX.MAX bits in smem + 1 redux after bar; (B) only threads whose local max
// equals gmax run the 8-wide equality scan + smem atomicMin (lowest global
// index = jnp.argmax first-occurrence). Point table staged in 128KB dynamic
// smem so the serial-dependent P[nxt] fetch is an LDS (29cyc) not an L2 hit.
// Distance math = reference's exact subtract-form fma chain.
extern __shared__ float4 sP[];                        // NPTS float4 = 128KB
__global__ void __launch_bounds__(1024, 1) fps_kernel() {
    const int b    = blockIdx.x;
    const int tid  = threadIdx.x;
    const int lane = tid & 31;
    const int wid  = tid >> 5;
    const float4* __restrict__ P = g_p4 + b * NPTS;

    // stage point table to smem (coalesced)
#pragma unroll
    for (int k = 0; k < 8; k++) sP[tid + k * 1024] = P[tid + k * 1024];

    // pair i holds points  n = i*2048 + tid*2 + {0,1}
    u64 X[4], Y[4], Z[4];
    float dist[8];
#pragma unroll
    for (int i = 0; i < 4; i++) {
        int n0 = i * 2048 + tid * 2;
        float4 a = P[n0];
        float4 c = P[n0 + 1];
        X[i] = pk2(a.x, c.x); Y[i] = pk2(a.y, c.y); Z[i] = pk2(a.z, c.z);
    }

    __shared__ unsigned swarp[2][32];
    __shared__ int      sidx[2];
    if (tid == 0) {
        sidx[0] = 0x7fffffff; sidx[1] = 0x7fffffff;
        g_fps[b * NPQ] = 0;
    }
    const int t2 = tid * 2;

    // d0 = ||x - x0||^2 (same fma chain as reference)
    float tmax;
    {
        float4 q0 = P[0];
        u64 ax = pk2(-q0.x, -q0.x), ay = pk2(-q0.y, -q0.y), az = pk2(-q0.z, -q0.z);
#pragma unroll
        for (int i = 0; i < 4; i++) {
            u64 dx = add2(X[i], ax), dy = add2(Y[i], ay), dz = add2(Z[i], az);
            u64 t = fma2(dz, dz, fma2(dy, dy, mul2(dx, dx)));
            upk2(t, dist[2 * i], dist[2 * i + 1]);
        }
        tmax = fmaxf(fmaxf(fmaxf(dist[0], dist[1]), fmaxf(dist[2], dist[3])),
                     fmaxf(fmaxf(dist[4], dist[5]), fmaxf(dist[6], dist[7])));
        unsigned wm = __reduce_max_sync(0xffffffffu, __float_as_uint(tmax));
        if (lane == 0) swarp[0][wid] = wm;
    }

    for (int j = 1; j < NPQ; j++) {
        __syncthreads();                               // barA: swarp/staging visible
        unsigned g = __reduce_max_sync(0xffffffffu, swarp[(j - 1) & 1][lane]);
        int slot = j & 1;
        if (__float_as_uint(tmax) == g) {              // ~1 thread per CTA
            float gf = __uint_as_float(g);
            int cand = 0x7fffffff;
#pragma unroll
            for (int k = 7; k >= 0; k--)               // keep lowest matching index
                if (dist[k] == gf) cand = ((k >> 1) << 11) + t2 + (k & 1);
            atomicMin(&sidx[slot], cand);
        }
        if (tid == 0) sidx[slot ^ 1] = 0x7fffffff;     // reset other slot
        __syncthreads();                               // barB: sidx[slot] final

        int nxt = sidx[slot];
        if (tid == 0) g_fps[b * NPQ + j] = nxt;

        float4 qq = sP[nxt];                           // LDS broadcast (29 cyc)
        u64 ax = pk2(-qq.x, -qq.x), ay = pk2(-qq.y, -qq.y), az = pk2(-qq.z, -qq.z);
#pragma unroll
        for (int i = 0; i < 4; i++) {
            u64 dx = add2(X[i], ax), dy = add2(Y[i], ay), dz = add2(Z[i], az);
            u64 t = fma2(dz, dz, fma2(dy, dy, mul2(dx, dx)));
            float a, c; upk2(t, a, c);
            dist[2 * i]     = fminf(dist[2 * i], a);
            dist[2 * i + 1] = fminf(dist[2 * i + 1], c);
        }
        tmax = fmaxf(fmaxf(fmaxf(dist[0], dist[1]), fmaxf(dist[2], dist[3])),
                     fmaxf(fmaxf(dist[4], dist[5]), fmaxf(dist[6], dist[7])));
        unsigned wm = __reduce_max_sync(0xffffffffu, __float_as_uint(tmax));
        if (lane == 0) swarp[j & 1][wid] = wm;
    }
}

// ---------------- gather sampled coords ----------------
__global__ void gather_q4_kernel() {
    int i = blockIdx.x * 256 + threadIdx.x;          // over NB*NPQ
    int b = i >> 11;
    g_q4[i] = g_p4[b * NPTS + g_fps[i]];
}

// ---------------- kNN (top-17 smallest, drop nearest) + mean-pool features ----------------
__global__ void __launch_bounds__(256) knn_group_kernel() {
    int gw   = blockIdx.x * 8 + (threadIdx.x >> 5);  // global query id = b*NPQ + qi
    int lane = threadIdx.x & 31;
    int b    = gw >> 11;

    float4 q = g_q4[gw];
    const float4* __restrict__ P = g_p4 + b * NPTS;

    float d[17]; int id[17];
#pragma unroll
    for (int t = 0; t < 17; t++) { d[t] = FLT_MAX; id[t] = 0x7fffffff; }

    // lane-local sorted top-17 over 256 strided candidates
    for (int t = 0; t < NPTS / 32; t++) {
        int n = t * 32 + lane;
        float4 p = P[n];
        float dot = __fmaf_rn(q.z, p.z, __fmaf_rn(q.y, p.y, q.x * p.x));
        float sq  = fmaxf(__fmaf_rn(-2.f, dot, q.w + p.w), 0.f);
        if (sq < d[16]) {
            d[16] = sq; id[16] = n;
#pragma unroll
            for (int jj = 16; jj > 0; jj--) {
                if (d[jj] < d[jj - 1]) {
                    float td = d[jj]; d[jj] = d[jj - 1]; d[jj - 1] = td;
                    int   ti = id[jj]; id[jj] = id[jj - 1]; id[jj - 1] = ti;
                }
            }
        }
    }

    // 17-round k-way merge across lanes; skip round 0 (self/nearest), accumulate 16 nbrs
    float4 acc = make_float4(0.f, 0.f, 0.f, 0.f);
    const float* Fb = g_feat_t + (size_t)b * NPTS * NCH;
    u64 key = ((u64)__float_as_uint(d[0]) << 32) | (unsigned)id[0];
    for (int r = 0; r < 17; r++) {
        u64 m = key;
#pragma unroll
        for (int s = 16; s > 0; s >>= 1) {
            u64 o = __shfl_xor_sync(0xffffffffu, m, s);
            m = (o < m) ? o : m;
        }
        if (r > 0) {
            int nn = (int)(unsigned)m;
            const float4* row = (const float4*)(Fb + (size_t)nn * NCH);
            float4 f = row[lane];
            acc.x += f.x; acc.y += f.y; acc.z += f.z; acc.w += f.w;
        }
        if (key == m) {
#pragma unroll
            for (int jj = 0; jj < 16; jj++) { d[jj] = d[jj + 1]; id[jj] = id[jj + 1]; }
            d[16] = FLT_MAX; id[16] = 0x7fffffff;
        }
        key = ((u64)__float_as_uint(d[0]) << 32) | (unsigned)id[0];
    }

    float4 o = make_float4(acc.x * 0.0625f, acc.y * 0.0625f,
                           acc.z * 0.0625f, acc.w * 0.0625f);
    ((float4*)(g_coarse_t + (size_t)gw * NCH))[lane] = o;
}

// ---------------- three_nn: 3 nearest sampled points + inverse-distance weights ----------------
__global__ void __launch_bounds__(256) three_nn_kernel() {
    int b = blockIdx.y;
    int n = blockIdx.x * 256 + threadIdx.x;
    __shared__ float4 sq4[NPQ];
    for (int i = threadIdx.x; i < NPQ; i += 256) sq4[i] = g_q4[b * NPQ + i];
    __syncthreads();

    float4 p = g_p4[b * NPTS + n];
    float d0 = FLT_MAX, d1 = FLT_MAX, d2 = FLT_MAX;
    int   i0 = 0, i1 = 0, i2 = 0;
    for (int j = 0; j < NPQ; j++) {
        float4 q = sq4[j];
        float dot = __fmaf_rn(q.z, p.z, __fmaf_rn(q.y, p.y, q.x * p.x));
        float s   = fmaxf(__fmaf_rn(-2.f, dot, q.w + p.w), 0.f);
        bool c2 = s < d2, c1 = s < d1, c0 = s < d0;
        d2 = c1 ? d1 : (c2 ? s : d2);
        i2 = c1 ? i1 : (c2 ? j : i2);
        d1 = c0 ? d0 : (c1 ? s : d1);
        i1 = c0 ? i0 : (c1 ? j : i1);
        d0 = c0 ? s : d0;
        i0 = c0 ? j : i0;
    }
    d0 = fmaxf(d0, 1e-10f); d1 = fmaxf(d1, 1e-10f); d2 = fmaxf(d2, 1e-10f);
    float v0 = __fdiv_rn(1.f, d0 + 1e-8f);
    float v1 = __fdiv_rn(1.f, d1 + 1e-8f);
    float v2 = __fdiv_rn(1.f, d2 + 1e-8f);
    float ss = v0 + v1 + v2;
    int o = (b * NPTS + n) * 3;
    g_i3[o] = i0; g_i3[o + 1] = i1; g_i3[o + 2] = i2;
    g_w3[o]     = __fdiv_rn(v0, ss);
    g_w3[o + 1] = __fdiv_rn(v1, ss);
    g_w3[o + 2] = __fdiv_rn(v2, ss);
}

// ---------------- interpolate: out[b,c,n] = sum_k w_k * coarse[b, i3_k, c] ----------------
__global__ void __launch_bounds__(256) interp_kernel(float* __restrict__ out) {
    int b    = blockIdx.y;
    int n    = blockIdx.x * 8 + threadIdx.y;
    int lane = threadIdx.x;                           // float4-channel index
    int o = (b * NPTS + n) * 3;
    int a0 = g_i3[o], a1 = g_i3[o + 1], a2 = g_i3[o + 2];
    float w0 = g_w3[o], w1 = g_w3[o + 1], w2 = g_w3[o + 2];

    const float4* C = (const float4*)g_coarse_t + (size_t)b * NPQ * (NCH / 4);
    float4 f0 = C[a0 * (NCH / 4) + lane];
    float4 f1 = C[a1 * (NCH / 4) + lane];
    float4 f2 = C[a2 * (NCH / 4) + lane];

    float4 r;
    r.x = __fmaf_rn(f2.x, w2, __fmaf_rn(f1.x, w1, f0.x * w0));
    r.y = __fmaf_rn(f2.y, w2, __fmaf_rn(f1.y, w1, f0.y * w0));
    r.z = __fmaf_rn(f2.z, w2, __fmaf_rn(f1.z, w1, f0.z * w0));
    r.w = __fmaf_rn(f2.w, w2, __fmaf_rn(f1.w, w1, f0.w * w0));

    float* op = out + (size_t)b * NCH * NPTS + n;
    int c = lane * 4;
    op[(size_t)(c + 0) * NPTS] = r.x;
    op[(size_t)(c + 1) * NPTS] = r.y;
    op[(size_t)(c + 2) * NPTS] = r.z;
    op[(size_t)(c + 3) * NPTS] = r.w;
}

// ---------------- launch ----------------
extern "C" void kernel_launch(void* const* d_in, const int* in_sizes, int n_in,
                              void* d_out, int out_size) {
    const float* points   = (const float*)d_in[0];
    const float* features = (const float*)d_in[1];
    for (int i = 0; i < n_in; i++) {
        if (in_sizes[i] == NB * NPTS * 3)            points   = (const float*)d_in[i];
        else if (in_sizes[i] == NB * NCH * NPTS)     features = (const float*)d_in[i];
    }
    float* out = (float*)d_out;

    const int fps_smem = NPTS * (int)sizeof(float4);   // 128KB
    cudaFuncSetAttribute(fps_kernel, cudaFuncAttributeMaxDynamicSharedMemorySize, fps_smem);

    prep_kernel<<<(NB * NPTS) / 256, 256>>>(points);
    transpose_kernel<<<dim3(NPTS / 32, NCH / 32, NB), dim3(32, 32)>>>(features);
    fps_kernel<<<NB, 1024, fps_smem>>>();
    gather_q4_kernel<<<(NB * NPQ) / 256, 256>>>();
    knn_group_kernel<<<(NB * NPQ) / 8, 256>>>();
    three_nn_kernel<<<dim3(NPTS / 256, NB), 256>>>();
    interp_kernel<<<dim3(NPTS / 8, NB), dim3(32, 8)>>>(out);
}

// round 6
// speedup vs baseline: 3.4768x; 1.0159x over previous
#include <cuda_runtime.h>
#include <cstdint>
#include <float.h>

#define NB    4
#define NPTS  8192
#define NPQ   2048
#define NCH   128

// ---------------- device scratch (statically allocated; no cudaMalloc) ----------------
__device__ float4 g_p4[NB * NPTS];                    // (x,y,z,|p|^2)
__device__ float4 g_q4[NB * NPQ];                     // sampled points
__device__ int    g_fps[NB * NPQ];
__device__ int    g_ord[NB * NPTS];                   // morton-sorted original indices
__device__ float  g_feat_t[(size_t)NB * NPTS * NCH];  // features transposed [B,N,C]
__device__ float  g_coarse_t[(size_t)NB * NPQ * NCH]; // pooled features [B,q,C]
__device__ int    g_i3[NB * NPTS * 3];
__device__ float  g_w3[NB * NPTS * 3];

typedef unsigned long long u64;

// ---------------- packed f32x2 helpers ----------------
__device__ __forceinline__ u64 pk2(float a, float b) {
    u64 r; asm("mov.b64 %0, {%1,%2};" : "=l"(r) : "f"(a), "f"(b)); return r;
}
__device__ __forceinline__ void upk2(u64 v, float& a, float& b) {
    asm("mov.b64 {%0,%1}, %2;" : "=f"(a), "=f"(b) : "l"(v));
}
__device__ __forceinline__ u64 add2(u64 a, u64 b) {
    u64 r; asm("add.rn.f32x2 %0, %1, %2;" : "=l"(r) : "l"(a), "l"(b)); return r;
}
__device__ __forceinline__ u64 mul2(u64 a, u64 b) {
    u64 r; asm("mul.rn.f32x2 %0, %1, %2;" : "=l"(r) : "l"(a), "l"(b)); return r;
}
__device__ __forceinline__ u64 fma2(u64 a, u64 b, u64 c) {
    u64 r; asm("fma.rn.f32x2 %0, %1, %2, %3;" : "=l"(r) : "l"(a), "l"(b), "l"(c)); return r;
}

// ---------------- prep: pack points + squared norm ----------------
__global__ void prep_kernel(const float* __restrict__ pts) {
    int i = blockIdx.x * 256 + threadIdx.x;          // over NB*NPTS
    float x = pts[3 * i], y = pts[3 * i + 1], z = pts[3 * i + 2];
    float nr = __fmaf_rn(z, z, __fmaf_rn(y, y, x * x));
    g_p4[i] = make_float4(x, y, z, nr);
}

// ---------------- transpose features [B,C,N] -> [B,N,C] ----------------
__global__ void transpose_kernel(const float* __restrict__ f) {
    __shared__ float tile[32][33];
    int b = blockIdx.z;
    int c0 = blockIdx.y * 32, n0 = blockIdx.x * 32;
    tile[threadIdx.y][threadIdx.x] =
        f[((size_t)b * NCH + c0 + threadIdx.y) * NPTS + n0 + threadIdx.x];
    __syncthreads();
    g_feat_t[((size_t)b * NPTS + n0 + threadIdx.y) * NCH + c0 + threadIdx.x] =
        tile[threadIdx.x][threadIdx.y];
}

// ---------------- morton sort: one CTA per batch, bitonic over 8192 u64 keys ----------------
__device__ __forceinline__ unsigned expand_bits(unsigned v) {
    v = (v | (v << 16)) & 0x030000FFu;
    v = (v | (v << 8))  & 0x0300F00Fu;
    v = (v | (v << 4))  & 0x030C30C3u;
    v = (v | (v << 2))  & 0x09249249u;
    return v;
}
__global__ void __launch_bounds__(1024, 1) sort_kernel() {
    extern __shared__ u64 sk[];                       // 8192 u64 = 64KB
    const int b = blockIdx.x, tid = threadIdx.x;
#pragma unroll
    for (int k = 0; k < 8; k++) {
        int i = tid + k * 1024;
        float4 p = g_p4[b * NPTS + i];
        unsigned mx = (unsigned)fminf(fmaxf((p.x + 5.f) * 102.4f, 0.f), 1023.f);
        unsigned my = (unsigned)fminf(fmaxf((p.y + 5.f) * 102.4f, 0.f), 1023.f);
        unsigned mz = (unsigned)fminf(fmaxf((p.z + 5.f) * 102.4f, 0.f), 1023.f);
        unsigned code = expand_bits(mx) | (expand_bits(my) << 1) | (expand_bits(mz) << 2);
        sk[i] = ((u64)code << 32) | (unsigned)i;
    }
    for (int k2 = 2; k2 <= NPTS; k2 <<= 1) {
        for (int jj = k2 >> 1; jj > 0; jj >>= 1) {
            __syncthreads();
#pragma unroll 4
            for (int t = tid; t < NPTS / 2; t += 1024) {
                int i = ((t & ~(jj - 1)) << 1) | (t & (jj - 1));
                int l = i | jj;
                u64 a = sk[i], c = sk[l];
                bool asc = ((i & k2) == 0);
                if ((a > c) == asc) { sk[i] = c; sk[l] = a; }
            }
        }
    }
    __syncthreads();
#pragma unroll
    for (int k = 0; k < 8; k++) {
        int i = tid + k * 1024;
        g_ord[b * NPTS + i] = (int)(unsigned)sk[i];
    }
}

// ---------------- FPS: one CTA/batch, warp-granular spatial pruning ----------------
// Warp w owns 256 morton-adjacent points (bbox computed once). Per iter a warp
// updates its dists only if boxdist2(q) < wmax*1.00001 (conservative margin >>
// fp rounding of the 6-op chains); otherwise dists/tmax/posted wmax stay valid.
// Update math = reference's exact subtract-form fma chain; argmax tie rule =
// lowest ORIGINAL index (per-thread scan reads sOrd, atomicMin across CTA).
extern __shared__ char fsmem[];                       // sP 128KB | sOrd 32KB
__global__ void __launch_bounds__(1024, 1) fps_kernel() {
    float4* sP   = (float4*)fsmem;
    int*    sOrd = (int*)(fsmem + NPTS * sizeof(float4));
    const int b    = blockIdx.x;
    const int tid  = threadIdx.x;
    const int lane = tid & 31;
    const int wid  = tid >> 5;
    const float4* __restrict__ P = g_p4 + b * NPTS;

    // stage original-order table + sorted index list (coalesced)
#pragma unroll
    for (int k = 0; k < 8; k++) {
        sP[tid + k * 1024]   = P[tid + k * 1024];
        sOrd[tid + k * 1024] = g_ord[b * NPTS + tid + k * 1024];
    }
    __shared__ unsigned swarp[32];
    __shared__ int      sidx[2];
    if (tid == 0) {
        sidx[0] = 0x7fffffff; sidx[1] = 0x7fffffff;
        g_fps[b * NPQ] = 0;
    }
    __syncthreads();

    // gather 8 points/thread from sorted order; sorted pos of reg k:
    //   sp(k) = wid*256 + (k>>1)*64 + lane*2 + (k&1)
    const int wbase = wid * 256 + lane * 2;
    u64 X[4], Y[4], Z[4];
    float px[8], py[8], pz[8], dist[8];
#pragma unroll
    for (int i = 0; i < 4; i++) {
        float4 a = sP[sOrd[wbase + i * 64]];
        float4 c = sP[sOrd[wbase + i * 64 + 1]];
        px[2*i] = a.x; py[2*i] = a.y; pz[2*i] = a.z;
        px[2*i+1] = c.x; py[2*i+1] = c.y; pz[2*i+1] = c.z;
        X[i] = pk2(a.x, c.x); Y[i] = pk2(a.y, c.y); Z[i] = pk2(a.z, c.z);
    }
    // warp bbox (once)
    float blx = px[0], bhx = px[0], bly = py[0], bhy = py[0], blz = pz[0], bhz = pz[0];
#pragma unroll
    for (int k = 1; k < 8; k++) {
        blx = fminf(blx, px[k]); bhx = fmaxf(bhx, px[k]);
        bly = fminf(bly, py[k]); bhy = fmaxf(bhy, py[k]);
        blz = fminf(blz, pz[k]); bhz = fmaxf(bhz, pz[k]);
    }
#pragma unroll
    for (int s = 16; s > 0; s >>= 1) {
        blx = fminf(blx, __shfl_xor_sync(0xffffffffu, blx, s));
        bhx = fmaxf(bhx, __shfl_xor_sync(0xffffffffu, bhx, s));
        bly = fminf(bly, __shfl_xor_sync(0xffffffffu, bly, s));
        bhy = fmaxf(bhy, __shfl_xor_sync(0xffffffffu, bhy, s));
        blz = fminf(blz, __shfl_xor_sync(0xffffffffu, blz, s));
        bhz = fmaxf(bhz, __shfl_xor_sync(0xffffffffu, bhz, s));
    }

    // iteration 0: d0 = ||x - x0||^2 (reference's fma chain), post wmax
    float tmax, wmaxf;
    {
        float4 q0 = sP[0];
        u64 ax = pk2(-q0.x, -q0.x), ay = pk2(-q0.y, -q0.y), az = pk2(-q0.z, -q0.z);
#pragma unroll
        for (int i = 0; i < 4; i++) {
            u64 dx = add2(X[i], ax), dy = add2(Y[i], ay), dz = add2(Z[i], az);
            u64 t = fma2(dz, dz, fma2(dy, dy, mul2(dx, dx)));
            upk2(t, dist[2 * i], dist[2 * i + 1]);
        }
        tmax = fmaxf(fmaxf(fmaxf(dist[0], dist[1]), fmaxf(dist[2], dist[3])),
                     fmaxf(fmaxf(dist[4], dist[5]), fmaxf(dist[6], dist[7])));
        unsigned wm = __reduce_max_sync(0xffffffffu, __float_as_uint(tmax));
        wmaxf = __uint_as_float(wm);
        if (lane == 0) swarp[wid] = wm;
    }

    for (int j = 1; j < NPQ; j++) {
        __syncthreads();                               // barA: swarp visible
        unsigned g = __reduce_max_sync(0xffffffffu, swarp[lane]);
        int slot = j & 1;
        if (__float_as_uint(tmax) == g) {              // ~1 thread per CTA
            float gf = __uint_as_float(g);
            int cand = 0x7fffffff;
#pragma unroll
            for (int k = 0; k < 8; k++)
                if (dist[k] == gf) {
                    int oi = sOrd[wbase + (k >> 1) * 64 + (k & 1)];
                    cand = min(cand, oi);
                }
            atomicMin(&sidx[slot], cand);
        }
        if (tid == 0) sidx[slot ^ 1] = 0x7fffffff;
        __syncthreads();                               // barB: sidx final

        int nxt = sidx[slot];
        if (tid == 0) g_fps[b * NPQ + j] = nxt;

        float4 qq = sP[nxt];                           // LDS broadcast
        // warp-uniform box distance to q
        float dxb = fmaxf(fmaxf(blx - qq.x, qq.x - bhx), 0.f);
        float dyb = fmaxf(fmaxf(bly - qq.y, qq.y - bhy), 0.f);
        float dzb = fmaxf(fmaxf(blz - qq.z, qq.z - bhz), 0.f);
        float boxd2 = __fmaf_rn(dzb, dzb, __fmaf_rn(dyb, dyb, dxb * dxb));

        if (boxd2 < wmaxf * 1.00001f) {                // conservative: update
            u64 ax = pk2(-qq.x, -qq.x), ay = pk2(-qq.y, -qq.y), az = pk2(-qq.z, -qq.z);
#pragma unroll
            for (int i = 0; i < 4; i++) {
                u64 dx = add2(X[i], ax), dy = add2(Y[i], ay), dz = add2(Z[i], az);
                u64 t = fma2(dz, dz, fma2(dy, dy, mul2(dx, dx)));
                float a, c; upk2(t, a, c);
                dist[2 * i]     = fminf(dist[2 * i], a);
                dist[2 * i + 1] = fminf(dist[2 * i + 1], c);
            }
            tmax = fmaxf(fmaxf(fmaxf(dist[0], dist[1]), fmaxf(dist[2], dist[3])),
                         fmaxf(fmaxf(dist[4], dist[5]), fmaxf(dist[6], dist[7])));
            unsigned wm = __reduce_max_sync(0xffffffffu, __float_as_uint(tmax));
            wmaxf = __uint_as_float(wm);
            if (lane == 0) swarp[wid] = wm;            // skipped warps keep old post
        }
    }
}

// ---------------- gather sampled coords ----------------
__global__ void gather_q4_kernel() {
    int i = blockIdx.x * 256 + threadIdx.x;          // over NB*NPQ
    int b = i >> 11;
    g_q4[i] = g_p4[b * NPTS + g_fps[i]];
}

// ---------------- kNN (top-17 smallest, drop nearest) + mean-pool features ----------------
__global__ void __launch_bounds__(256) knn_group_kernel() {
    int gw   = blockIdx.x * 8 + (threadIdx.x >> 5);  // global query id = b*NPQ + qi
    int lane = threadIdx.x & 31;
    int b    = gw >> 11;

    float4 q = g_q4[gw];
    const float4* __restrict__ P = g_p4 + b * NPTS;

    float d[17]; int id[17];
#pragma unroll
    for (int t = 0; t < 17; t++) { d[t] = FLT_MAX; id[t] = 0x7fffffff; }

    // lane-local sorted top-17 over 256 strided candidates
    for (int t = 0; t < NPTS / 32; t++) {
        int n = t * 32 + lane;
        float4 p = P[n];
        float dot = __fmaf_rn(q.z, p.z, __fmaf_rn(q.y, p.y, q.x * p.x));
        float sq  = fmaxf(__fmaf_rn(-2.f, dot, q.w + p.w), 0.f);
        if (sq < d[16]) {
            d[16] = sq; id[16] = n;
#pragma unroll
            for (int jj = 16; jj > 0; jj--) {
                if (d[jj] < d[jj - 1]) {
                    float td = d[jj]; d[jj] = d[jj - 1]; d[jj - 1] = td;
                    int   ti = id[jj]; id[jj] = id[jj - 1]; id[jj - 1] = ti;
                }
            }
        }
    }

    // 17-round k-way merge across lanes; skip round 0 (self/nearest), accumulate 16 nbrs
    float4 acc = make_float4(0.f, 0.f, 0.f, 0.f);
    const float* Fb = g_feat_t + (size_t)b * NPTS * NCH;
    u64 key = ((u64)__float_as_uint(d[0]) << 32) | (unsigned)id[0];
    for (int r = 0; r < 17; r++) {
        u64 m = key;
#pragma unroll
        for (int s = 16; s > 0; s >>= 1) {
            u64 o = __shfl_xor_sync(0xffffffffu, m, s);
            m = (o < m) ? o : m;
        }
        if (r > 0) {
            int nn = (int)(unsigned)m;
            const float4* row = (const float4*)(Fb + (size_t)nn * NCH);
            float4 f = row[lane];
            acc.x += f.x; acc.y += f.y; acc.z += f.z; acc.w += f.w;
        }
        if (key == m) {
#pragma unroll
            for (int jj = 0; jj < 16; jj++) { d[jj] = d[jj + 1]; id[jj] = id[jj + 1]; }
            d[16] = FLT_MAX; id[16] = 0x7fffffff;
        }
        key = ((u64)__float_as_uint(d[0]) << 32) | (unsigned)id[0];
    }

    float4 o = make_float4(acc.x * 0.0625f, acc.y * 0.0625f,
                           acc.z * 0.0625f, acc.w * 0.0625f);
    ((float4*)(g_coarse_t + (size_t)gw * NCH))[lane] = o;
}

// ---------------- three_nn: 3 nearest sampled points + inverse-distance weights ----------------
__global__ void __launch_bounds__(256) three_nn_kernel() {
    int b = blockIdx.y;
    int n = blockIdx.x * 256 + threadIdx.x;
    __shared__ float4 sq4[NPQ];
    for (int i = threadIdx.x; i < NPQ; i += 256) sq4[i] = g_q4[b * NPQ + i];
    __syncthreads();

    float4 p = g_p4[b * NPTS + n];
    float d0 = FLT_MAX, d1 = FLT_MAX, d2 = FLT_MAX;
    int   i0 = 0, i1 = 0, i2 = 0;
    for (int j = 0; j < NPQ; j++) {
        float4 q = sq4[j];
        float dot = __fmaf_rn(q.z, p.z, __fmaf_rn(q.y, p.y, q.x * p.x));
        float s   = fmaxf(__fmaf_rn(-2.f, dot, q.w + p.w), 0.f);
        bool c2 = s < d2, c1 = s < d1, c0 = s < d0;
        d2 = c1 ? d1 : (c2 ? s : d2);
        i2 = c1 ? i1 : (c2 ? j : i2);
        d1 = c0 ? d0 : (c1 ? s : d1);
        i1 = c0 ? i0 : (c1 ? j : i1);
        d0 = c0 ? s : d0;
        i0 = c0 ? j : i0;
    }
    d0 = fmaxf(d0, 1e-10f); d1 = fmaxf(d1, 1e-10f); d2 = fmaxf(d2, 1e-10f);
    float v0 = __fdiv_rn(1.f, d0 + 1e-8f);
    float v1 = __fdiv_rn(1.f, d1 + 1e-8f);
    float v2 = __fdiv_rn(1.f, d2 + 1e-8f);
    float ss = v0 + v1 + v2;
    int o = (b * NPTS + n) * 3;
    g_i3[o] = i0; g_i3[o + 1] = i1; g_i3[o + 2] = i2;
    g_w3[o]     = __fdiv_rn(v0, ss);
    g_w3[o + 1] = __fdiv_rn(v1, ss);
    g_w3[o + 2] = __fdiv_rn(v2, ss);
}

// ---------------- interpolate: out[b,c,n] = sum_k w_k * coarse[b, i3_k, c] ----------------
__global__ void __launch_bounds__(256) interp_kernel(float* __restrict__ out) {
    int b    = blockIdx.y;
    int n    = blockIdx.x * 8 + threadIdx.y;
    int lane = threadIdx.x;                           // float4-channel index
    int o = (b * NPTS + n) * 3;
    int a0 = g_i3[o], a1 = g_i3[o + 1], a2 = g_i3[o + 2];
    float w0 = g_w3[o], w1 = g_w3[o + 1], w2 = g_w3[o + 2];

    const float4* C = (const float4*)g_coarse_t + (size_t)b * NPQ * (NCH / 4);
    float4 f0 = C[a0 * (NCH / 4) + lane];
    float4 f1 = C[a1 * (NCH / 4) + lane];
    float4 f2 = C[a2 * (NCH / 4) + lane];

    float4 r;
    r.x = __fmaf_rn(f2.x, w2, __fmaf_rn(f1.x, w1, f0.x * w0));
    r.y = __fmaf_rn(f2.y, w2, __fmaf_rn(f1.y, w1, f0.y * w0));
    r.z = __fmaf_rn(f2.z, w2, __fmaf_rn(f1.z, w1, f0.z * w0));
    r.w = __fmaf_rn(f2.w, w2, __fmaf_rn(f1.w, w1, f0.w * w0));

    float* op = out + (size_t)b * NCH * NPTS + n;
    int c = lane * 4;
    op[(size_t)(c + 0) * NPTS] = r.x;
    op[(size_t)(c + 1) * NPTS] = r.y;
    op[(size_t)(c + 2) * NPTS] = r.z;
    op[(size_t)(c + 3) * NPTS] = r.w;
}

// ---------------- launch ----------------
extern "C" void kernel_launch(void* const* d_in, const int* in_sizes, int n_in,
                              void* d_out, int out_size) {
    const float* points   = (const float*)d_in[0];
    const float* features = (const float*)d_in[1];
    for (int i = 0; i < n_in; i++) {
        if (in_sizes[i] == NB * NPTS * 3)            points   = (const float*)d_in[i];
        else if (in_sizes[i] == NB * NCH * NPTS)     features = (const float*)d_in[i];
    }
    float* out = (float*)d_out;

    const int fps_smem  = NPTS * (int)sizeof(float4) + NPTS * (int)sizeof(int); // 160KB
    const int sort_smem = NPTS * (int)sizeof(u64);                              // 64KB
    cudaFuncSetAttribute(fps_kernel,  cudaFuncAttributeMaxDynamicSharedMemorySize, fps_smem);
    cudaFuncSetAttribute(sort_kernel, cudaFuncAttributeMaxDynamicSharedMemorySize, sort_smem);

    prep_kernel<<<(NB * NPTS) / 256, 256>>>(points);
    transpose_kernel<<<dim3(NPTS / 32, NCH / 32, NB), dim3(32, 32)>>>(features);
    sort_kernel<<<NB, 1024, sort_smem>>>();
    fps_kernel<<<NB, 1024, fps_smem>>>();
    gather_q4_kernel<<<(NB * NPQ) / 256, 256>>>();
    knn_group_kernel<<<(NB * NPQ) / 8, 256>>>();
    three_nn_kernel<<<dim3(NPTS / 256, NB), 256>>>();
    interp_kernel<<<dim3(NPTS / 8, NB), dim3(32, 8)>>>(out);
}

// round 7
// speedup vs baseline: 4.0883x; 1.1759x over previous
#include <cuda_runtime.h>
#include <cstdint>
#include <float.h>

#define NB    4
#define NPTS  8192
#define NPQ   2048
#define NCH   128

// ---------------- device scratch (statically allocated; no cudaMalloc) ----------------
__device__ float4 g_p4[NB * NPTS];                    // (x,y,z,|p|^2)
__device__ float4 g_q4[NB * NPQ];                     // sampled points
__device__ int    g_fps[NB * NPQ];
__device__ int    g_ord[NB * NPTS];                   // morton-binned original indices
__device__ float  g_feat_t[(size_t)NB * NPTS * NCH];  // features transposed [B,N,C]
__device__ float  g_coarse_t[(size_t)NB * NPQ * NCH]; // pooled features [B,q,C]
__device__ int    g_i3[NB * NPTS * 3];
__device__ float  g_w3[NB * NPTS * 3];

typedef unsigned long long u64;
__device__ u64 g_nn[(size_t)NB * NPTS * 12];          // three_nn partials: 4 chunks x 3 keys

// ---------------- packed f32x2 helpers ----------------
__device__ __forceinline__ u64 pk2(float a, float b) {
    u64 r; asm("mov.b64 %0, {%1,%2};" : "=l"(r) : "f"(a), "f"(b)); return r;
}
__device__ __forceinline__ void upk2(u64 v, float& a, float& b) {
    asm("mov.b64 {%0,%1}, %2;" : "=f"(a), "=f"(b) : "l"(v));
}
__device__ __forceinline__ u64 add2(u64 a, u64 b) {
    u64 r; asm("add.rn.f32x2 %0, %1, %2;" : "=l"(r) : "l"(a), "l"(b)); return r;
}
__device__ __forceinline__ u64 mul2(u64 a, u64 b) {
    u64 r; asm("mul.rn.f32x2 %0, %1, %2;" : "=l"(r) : "l"(a), "l"(b)); return r;
}
__device__ __forceinline__ u64 fma2(u64 a, u64 b, u64 c) {
    u64 r; asm("fma.rn.f32x2 %0, %1, %2, %3;" : "=l"(r) : "l"(a), "l"(b), "l"(c)); return r;
}

// ---------------- prep: pack points + squared norm ----------------
__global__ void prep_kernel(const float* __restrict__ pts) {
    int i = blockIdx.x * 256 + threadIdx.x;          // over NB*NPTS
    float x = pts[3 * i], y = pts[3 * i + 1], z = pts[3 * i + 2];
    float nr = __fmaf_rn(z, z, __fmaf_rn(y, y, x * x));
    g_p4[i] = make_float4(x, y, z, nr);
}

// ---------------- transpose features [B,C,N] -> [B,N,C] ----------------
__global__ void transpose_kernel(const float* __restrict__ f) {
    __shared__ float tile[32][33];
    int b = blockIdx.z;
    int c0 = blockIdx.y * 32, n0 = blockIdx.x * 32;
    tile[threadIdx.y][threadIdx.x] =
        f[((size_t)b * NCH + c0 + threadIdx.y) * NPTS + n0 + threadIdx.x];
    __syncthreads();
    g_feat_t[((size_t)b * NPTS + n0 + threadIdx.y) * NCH + c0 + threadIdx.x] =
        tile[threadIdx.x][threadIdx.y];
}

// ---------------- morton binning: counting sort into 4096 cells (16^3) ----------------
__device__ __forceinline__ unsigned eb4(unsigned v) {  // 4 bits -> stride-3 positions
    return (v & 1u) | ((v & 2u) << 2) | ((v & 4u) << 4) | ((v & 8u) << 6);
}
__global__ void __launch_bounds__(1024, 1) sort_kernel() {
    __shared__ unsigned hist[4096];
    __shared__ unsigned wsum[32];
    const int b = blockIdx.x, tid = threadIdx.x;
    const int lane = tid & 31, wid = tid >> 5;
    for (int i = tid; i < 4096; i += 1024) hist[i] = 0;
    __syncthreads();
    unsigned code[8];
#pragma unroll
    for (int k = 0; k < 8; k++) {
        int i = tid + k * 1024;
        float4 p = g_p4[b * NPTS + i];
        unsigned mx = (unsigned)fminf(fmaxf((p.x + 4.f) * 2.f, 0.f), 15.f);
        unsigned my = (unsigned)fminf(fmaxf((p.y + 4.f) * 2.f, 0.f), 15.f);
        unsigned mz = (unsigned)fminf(fmaxf((p.z + 4.f) * 2.f, 0.f), 15.f);
        code[k] = eb4(mx) | (eb4(my) << 1) | (eb4(mz) << 2);
        atomicAdd(&hist[code[k]], 1u);
    }
    __syncthreads();
    // exclusive scan over 4096 bins (thread owns 4 consecutive)
    unsigned h0 = hist[4 * tid], h1 = hist[4 * tid + 1],
             h2 = hist[4 * tid + 2], h3 = hist[4 * tid + 3];
    unsigned s = h0 + h1 + h2 + h3, si = s;
#pragma unroll
    for (int d = 1; d < 32; d <<= 1) {
        unsigned v = __shfl_up_sync(0xffffffffu, si, d);
        if (lane >= d) si += v;
    }
    if (lane == 31) wsum[wid] = si;
    __syncthreads();
    if (wid == 0) {
        unsigned v = wsum[lane], vi = v;
#pragma unroll
        for (int d = 1; d < 32; d <<= 1) {
            unsigned t = __shfl_up_sync(0xffffffffu, vi, d);
            if (lane >= d) vi += t;
        }
        wsum[lane] = vi;
    }
    __syncthreads();
    unsigned base = (wid ? wsum[wid - 1] : 0u) + si - s;
    hist[4 * tid]     = base;
    hist[4 * tid + 1] = base + h0;
    hist[4 * tid + 2] = base + h0 + h1;
    hist[4 * tid + 3] = base + h0 + h1 + h2;
    __syncthreads();
#pragma unroll
    for (int k = 0; k < 8; k++) {
        int i = tid + k * 1024;
        unsigned slot = atomicAdd(&hist[code[k]], 1u);
        g_ord[b * NPTS + slot] = i;
    }
}

// ---------------- FPS: one CTA/batch, warp pruning, 1 barrier/iter ----------------
// Warp owns 256 morton-adjacent points (bbox once). Every iter each warp posts
// its (maxdistbits, min-orig-index) key to a double-buffered smem slot (skipped
// warps repost their still-valid key: dists unchanged). After the single bar,
// every warp LDS.64s the 32 keys and REDUX-reduces to nxt (ties -> lowest
// original index = jnp.argmax first-occurrence). Skip margin 1e-5 >> fp
// rounding of the 6-op chains, so reference-visible min-updates never skipped;
// results are independent of the g_ord permutation. Update math = reference's
// exact subtract-form fma chain.
__global__ void __launch_bounds__(1024, 1) fps_kernel() {
    extern __shared__ char fsmem[];                   // sP 128KB | sOrd 32KB
    float4* sP   = (float4*)fsmem;
    int*    sOrd = (int*)(fsmem + NPTS * sizeof(float4));
    const int b    = blockIdx.x;
    const int tid  = threadIdx.x;
    const int lane = tid & 31;
    const int wid  = tid >> 5;
    const float4* __restrict__ P = g_p4 + b * NPTS;

#pragma unroll
    for (int k = 0; k < 8; k++) {
        sP[tid + k * 1024]   = P[tid + k * 1024];
        sOrd[tid + k * 1024] = g_ord[b * NPTS + tid + k * 1024];
    }
    __shared__ u64 skey[2][32];
    if (tid == 0) g_fps[b * NPQ] = 0;
    __syncthreads();

    const int wbase = wid * 256 + lane * 2;
    u64 X[4], Y[4], Z[4];
    float dist[8];
    unsigned ordp[4];                                 // 2x16b packed original indices
    float blx = FLT_MAX, bhx = -FLT_MAX, bly = FLT_MAX, bhy = -FLT_MAX,
          blz = FLT_MAX, bhz = -FLT_MAX;
#pragma unroll
    for (int i = 0; i < 4; i++) {
        int o0 = sOrd[wbase + i * 64], o1 = sOrd[wbase + i * 64 + 1];
        ordp[i] = (unsigned)o0 | ((unsigned)o1 << 16);
        float4 a = sP[o0], c = sP[o1];
        X[i] = pk2(a.x, c.x); Y[i] = pk2(a.y, c.y); Z[i] = pk2(a.z, c.z);
        blx = fminf(blx, fminf(a.x, c.x)); bhx = fmaxf(bhx, fmaxf(a.x, c.x));
        bly = fminf(bly, fminf(a.y, c.y)); bhy = fmaxf(bhy, fmaxf(a.y, c.y));
        blz = fminf(blz, fminf(a.z, c.z)); bhz = fmaxf(bhz, fmaxf(a.z, c.z));
    }
#pragma unroll
    for (int s = 16; s > 0; s >>= 1) {
        blx = fminf(blx, __shfl_xor_sync(0xffffffffu, blx, s));
        bhx = fmaxf(bhx, __shfl_xor_sync(0xffffffffu, bhx, s));
        bly = fminf(bly, __shfl_xor_sync(0xffffffffu, bly, s));
        bhy = fmaxf(bhy, __shfl_xor_sync(0xffffffffu, bhy, s));
        blz = fminf(blz, __shfl_xor_sync(0xffffffffu, blz, s));
        bhz = fmaxf(bhz, __shfl_xor_sync(0xffffffffu, bhz, s));
    }

    u64 mykey;
    float wmaxf;
    {   // iteration 0: d0 = ||x - x0||^2
        float4 q0 = sP[0];
        u64 ax = pk2(-q0.x, -q0.x), ay = pk2(-q0.y, -q0.y), az = pk2(-q0.z, -q0.z);
#pragma unroll
        for (int i = 0; i < 4; i++) {
            u64 dx = add2(X[i], ax), dy = add2(Y[i], ay), dz = add2(Z[i], az);
            u64 t = fma2(dz, dz, fma2(dy, dy, mul2(dx, dx)));
            upk2(t, dist[2 * i], dist[2 * i + 1]);
        }
        float tmax = fmaxf(fmaxf(fmaxf(dist[0], dist[1]), fmaxf(dist[2], dist[3])),
                           fmaxf(fmaxf(dist[4], dist[5]), fmaxf(dist[6], dist[7])));
        unsigned wm = __reduce_max_sync(0xffffffffu, __float_as_uint(tmax));
        wmaxf = __uint_as_float(wm);
        unsigned cand = 0xffffffffu;
#pragma unroll
        for (int k = 0; k < 8; k++) {
            unsigned oi = (k & 1) ? (ordp[k >> 1] >> 16) : (ordp[k >> 1] & 0xffffu);
            if (dist[k] == wmaxf) cand = min(cand, oi);
        }
        unsigned widx = __reduce_min_sync(0xffffffffu, cand);
        mykey = ((u64)wm << 32) | widx;
        if (lane == 0) skey[0][wid] = mykey;
    }

    for (int j = 1; j < NPQ; j++) {
        __syncthreads();                               // prev-iter keys visible
        u64 k64 = skey[(j - 1) & 1][lane];
        unsigned hi = (unsigned)(k64 >> 32), lo = (unsigned)k64;
        unsigned g   = __reduce_max_sync(0xffffffffu, hi);
        unsigned cc  = (hi == g) ? lo : 0xffffffffu;
        unsigned nxt = __reduce_min_sync(0xffffffffu, cc);
        if (tid == 0) g_fps[b * NPQ + j] = (int)nxt;

        float4 qq = sP[nxt];                           // LDS broadcast
        float dxb = fmaxf(fmaxf(blx - qq.x, qq.x - bhx), 0.f);
        float dyb = fmaxf(fmaxf(bly - qq.y, qq.y - bhy), 0.f);
        float dzb = fmaxf(fmaxf(blz - qq.z, qq.z - bhz), 0.f);
        float boxd2 = __fmaf_rn(dzb, dzb, __fmaf_rn(dyb, dyb, dxb * dxb));

        if (boxd2 < wmaxf * 1.00001f) {                // conservative: update
            u64 ax = pk2(-qq.x, -qq.x), ay = pk2(-qq.y, -qq.y), az = pk2(-qq.z, -qq.z);
#pragma unroll
            for (int i = 0; i < 4; i++) {
                u64 dx = add2(X[i], ax), dy = add2(Y[i], ay), dz = add2(Z[i], az);
                u64 t = fma2(dz, dz, fma2(dy, dy, mul2(dx, dx)));
                float a, c; upk2(t, a, c);
                dist[2 * i]     = fminf(dist[2 * i], a);
                dist[2 * i + 1] = fminf(dist[2 * i + 1], c);
            }
            float tmax = fmaxf(fmaxf(fmaxf(dist[0], dist[1]), fmaxf(dist[2], dist[3])),
                               fmaxf(fmaxf(dist[4], dist[5]), fmaxf(dist[6], dist[7])));
            unsigned wm = __reduce_max_sync(0xffffffffu, __float_as_uint(tmax));
            wmaxf = __uint_as_float(wm);
            unsigned cand = 0xffffffffu;
#pragma unroll
            for (int k = 0; k < 8; k++) {
                unsigned oi = (k & 1) ? (ordp[k >> 1] >> 16) : (ordp[k >> 1] & 0xffffu);
                if (dist[k] == wmaxf) cand = min(cand, oi);
            }
            unsigned widx = __reduce_min_sync(0xffffffffu, cand);
            mykey = ((u64)wm << 32) | widx;
        }
        if (lane == 0) skey[j & 1][wid] = mykey;       // always post
    }
}

// ---------------- gather sampled coords ----------------
__global__ void gather_q4_kernel() {
    int i = blockIdx.x * 256 + threadIdx.x;          // over NB*NPQ
    int b = i >> 11;
    g_q4[i] = g_p4[b * NPTS + g_fps[i]];
}

// ---------------- kNN: warp-shared sorted top-17 + mean-pool ----------------
// 128 blocks; each stages the batch point table (128KB smem), 8 warps x 8
// queries. The global top-17 (lex key = (sqbits, idx), exact top_k tie rule)
// lives distributed in lanes 0..16; inserts only on true top-17 hits.
// Lane 0 = nearest (self) is skipped; lanes 1..16 accumulated in ascending
// order = reference's top_k order, so the float sum order matches.
__global__ void __launch_bounds__(256) knn_group_kernel() {
    extern __shared__ float4 sT[];                    // 8192 float4 = 128KB
    const int tid  = threadIdx.x;
    const int lane = tid & 31;
    const int w    = tid >> 5;
    const int b    = blockIdx.x >> 5;                 // 32 blocks per batch
    const int qb   = (blockIdx.x & 31) * 64;

#pragma unroll
    for (int k = 0; k < 32; k++) sT[tid + k * 256] = g_p4[b * NPTS + tid + k * 256];
    __syncthreads();

    const float* Fb = g_feat_t + (size_t)b * NPTS * NCH;
    for (int qi = 0; qi < 8; qi++) {
        int gw = b * NPQ + qb + w * 8 + qi;
        float4 q = g_q4[gw];
        u64 mykey = ~0ull, thr = ~0ull;
        for (int t = 0; t < NPTS / 32; t++) {
            int n = t * 32 + lane;
            float4 p = sT[n];
            float dot = __fmaf_rn(q.z, p.z, __fmaf_rn(q.y, p.y, q.x * p.x));
            float sq  = fmaxf(__fmaf_rn(-2.f, dot, q.w + p.w), 0.f);
            u64 cand = ((u64)__float_as_uint(sq) << 32) | (unsigned)n;
            unsigned ball = __ballot_sync(0xffffffffu, cand < thr);
            while (ball) {
                int src = __ffs(ball) - 1; ball &= ball - 1;
                u64 c = __shfl_sync(0xffffffffu, cand, src);
                unsigned pb = __ballot_sync(0xffffffffu, (lane < 17) && (c < mykey));
                if (pb) {
                    int pos = __ffs(pb) - 1;
                    u64 up = __shfl_up_sync(0xffffffffu, mykey, 1);
                    if (lane >= pos && lane < 17) mykey = (lane == pos) ? c : up;
                }
                thr = __shfl_sync(0xffffffffu, mykey, 16);
            }
        }
        float4 acc = make_float4(0.f, 0.f, 0.f, 0.f);
#pragma unroll 1
        for (int r = 1; r < 17; r++) {
            int nn = (int)(unsigned)__shfl_sync(0xffffffffu, mykey, r);
            float4 f = ((const float4*)(Fb + (size_t)nn * NCH))[lane];
            acc.x += f.x; acc.y += f.y; acc.z += f.z; acc.w += f.w;
        }
        float4 o = make_float4(acc.x * 0.0625f, acc.y * 0.0625f,
                               acc.z * 0.0625f, acc.w * 0.0625f);
        ((float4*)(g_coarse_t + (size_t)gw * NCH))[lane] = o;
    }
}

// ---------------- three_nn part: each chunk of 512 queries -> 3 lex keys ----------------
__global__ void __launch_bounds__(256) three_nn_part() {
    int b = blockIdx.y, c = blockIdx.z;
    int n = blockIdx.x * 256 + threadIdx.x;
    __shared__ float4 sq4[512];
    for (int i = threadIdx.x; i < 512; i += 256) sq4[i] = g_q4[b * NPQ + c * 512 + i];
    __syncthreads();

    float4 p = g_p4[b * NPTS + n];
    float d0 = FLT_MAX, d1 = FLT_MAX, d2 = FLT_MAX;
    int   i0 = 0, i1 = 0, i2 = 0;
    for (int j2 = 0; j2 < 512; j2++) {
        float4 q = sq4[j2];
        int j = c * 512 + j2;
        float dot = __fmaf_rn(q.z, p.z, __fmaf_rn(q.y, p.y, q.x * p.x));
        float s   = fmaxf(__fmaf_rn(-2.f, dot, q.w + p.w), 0.f);
        bool c2 = s < d2, c1 = s < d1, c0 = s < d0;
        d2 = c1 ? d1 : (c2 ? s : d2);
        i2 = c1 ? i1 : (c2 ? j : i2);
        d1 = c0 ? d0 : (c1 ? s : d1);
        i1 = c0 ? i0 : (c1 ? j : i1);
        d0 = c0 ? s : d0;
        i0 = c0 ? j : i0;
    }
    size_t o = ((size_t)(b * NPTS + n) * 4 + c) * 3;
    g_nn[o]     = ((u64)__float_as_uint(d0) << 32) | (unsigned)i0;
    g_nn[o + 1] = ((u64)__float_as_uint(d1) << 32) | (unsigned)i1;
    g_nn[o + 2] = ((u64)__float_as_uint(d2) << 32) | (unsigned)i2;
}

// ---------------- three_nn combine: merge 4 chunks, compute weights ----------------
__global__ void __launch_bounds__(256) three_nn_comb() {
    int i = blockIdx.x * 256 + threadIdx.x;           // over NB*NPTS
    u64 a0 = ~0ull, a1 = ~0ull, a2 = ~0ull;
#pragma unroll
    for (int c = 0; c < 12; c++) {
        u64 k = g_nn[(size_t)i * 12 + c];
        if (k < a0)      { a2 = a1; a1 = a0; a0 = k; }
        else if (k < a1) { a2 = a1; a1 = k; }
        else if (k < a2) { a2 = k; }
    }
    float d0 = fmaxf(__uint_as_float((unsigned)(a0 >> 32)), 1e-10f);
    float d1 = fmaxf(__uint_as_float((unsigned)(a1 >> 32)), 1e-10f);
    float d2 = fmaxf(__uint_as_float((unsigned)(a2 >> 32)), 1e-10f);
    float v0 = __fdiv_rn(1.f, d0 + 1e-8f);
    float v1 = __fdiv_rn(1.f, d1 + 1e-8f);
    float v2 = __fdiv_rn(1.f, d2 + 1e-8f);
    float ss = v0 + v1 + v2;
    int o = i * 3;
    g_i3[o] = (int)(unsigned)a0; g_i3[o + 1] = (int)(unsigned)a1; g_i3[o + 2] = (int)(unsigned)a2;
    g_w3[o]     = __fdiv_rn(v0, ss);
    g_w3[o + 1] = __fdiv_rn(v1, ss);
    g_w3[o + 2] = __fdiv_rn(v2, ss);
}

// ---------------- interpolate: out[b,c,n] = sum_k w_k * coarse[b, i3_k, c] ----------------
__global__ void __launch_bounds__(256) interp_kernel(float* __restrict__ out) {
    int b    = blockIdx.y;
    int n    = blockIdx.x * 8 + threadIdx.y;
    int lane = threadIdx.x;                           // float4-channel index
    int o = (b * NPTS + n) * 3;
    int a0 = g_i3[o], a1 = g_i3[o + 1], a2 = g_i3[o + 2];
    float w0 = g_w3[o], w1 = g_w3[o + 1], w2 = g_w3[o + 2];

    const float4* C = (const float4*)g_coarse_t + (size_t)b * NPQ * (NCH / 4);
    float4 f0 = C[a0 * (NCH / 4) + lane];
    float4 f1 = C[a1 * (NCH / 4) + lane];
    float4 f2 = C[a2 * (NCH / 4) + lane];

    float4 r;
    r.x = __fmaf_rn(f2.x, w2, __fmaf_rn(f1.x, w1, f0.x * w0));
    r.y = __fmaf_rn(f2.y, w2, __fmaf_rn(f1.y, w1, f0.y * w0));
    r.z = __fmaf_rn(f2.z, w2, __fmaf_rn(f1.z, w1, f0.z * w0));
    r.w = __fmaf_rn(f2.w, w2, __fmaf_rn(f1.w, w1, f0.w * w0));

    float* op = out + (size_t)b * NCH * NPTS + n;
    int c = lane * 4;
    op[(size_t)(c + 0) * NPTS] = r.x;
    op[(size_t)(c + 1) * NPTS] = r.y;
    op[(size_t)(c + 2) * NPTS] = r.z;
    op[(size_t)(c + 3) * NPTS] = r.w;
}

// ---------------- launch ----------------
extern "C" void kernel_launch(void* const* d_in, const int* in_sizes, int n_in,
                              void* d_out, int out_size) {
    const float* points   = (const float*)d_in[0];
    const float* features = (const float*)d_in[1];
    for (int i = 0; i < n_in; i++) {
        if (in_sizes[i] == NB * NPTS * 3)            points   = (const float*)d_in[i];
        else if (in_sizes[i] == NB * NCH * NPTS)     features = (const float*)d_in[i];
    }
    float* out = (float*)d_out;

    const int fps_smem = NPTS * (int)sizeof(float4) + NPTS * (int)sizeof(int); // 160KB
    const int knn_smem = NPTS * (int)sizeof(float4);                           // 128KB
    cudaFuncSetAttribute(fps_kernel,       cudaFuncAttributeMaxDynamicSharedMemorySize, fps_smem);
    cudaFuncSetAttribute(knn_group_kernel, cudaFuncAttributeMaxDynamicSharedMemorySize, knn_smem);

    prep_kernel<<<(NB * NPTS) / 256, 256>>>(points);
    transpose_kernel<<<dim3(NPTS / 32, NCH / 32, NB), dim3(32, 32)>>>(features);
    sort_kernel<<<NB, 1024>>>();
    fps_kernel<<<NB, 1024, fps_smem>>>();
    gather_q4_kernel<<<(NB * NPQ) / 256, 256>>>();
    knn_group_kernel<<<128, 256, knn_smem>>>();
    three_nn_part<<<dim3(NPTS / 256, NB, 4), 256>>>();
    three_nn_comb<<<(NB * NPTS) / 256, 256>>>();
    interp_kernel<<<dim3(NPTS / 8, NB), dim3(32, 8)>>>(out);
}